// round 1
// baseline (speedup 1.0000x reference)
#include <cuda_runtime.h>
#include <cstddef>

// ---------------- scratch (device globals; no allocations allowed) ----------
__device__ float g_a1[4096 * 5280];   // post-relu conv1: [b][32][11*15]
__device__ float g_a2[4096 * 2240];   // post-relu conv2: [b][64][5*7]
__device__ float g_a3[4096 * 960];    // post-relu conv3 (flatten CHW): [b][960]
__device__ float g_h [4096 * 512];    // post-relu fc1
__device__ float g_w1t[192 * 32];     // w1 transposed [k][oc]
__device__ float g_w2t[288 * 64];     // w2 transposed [k][oc]
__device__ float g_w3t[576 * 64];     // w3 transposed [k][oc]

// ---------------- prep: transpose weights + zero ave outputs ----------------
__global__ void prep_kernel(const float* __restrict__ w1,
                            const float* __restrict__ w2,
                            const float* __restrict__ w3,
                            float* __restrict__ aves /* 215 floats */) {
    int i = blockIdx.x * blockDim.x + threadIdx.x;
    if (i < 215) aves[i] = 0.0f;
    if (i < 6144)  { int oc = i / 192, k = i % 192; g_w1t[k * 32 + oc] = w1[i]; }
    if (i < 18432) { int oc = i / 288, k = i % 288; g_w2t[k * 64 + oc] = w2[i]; }
    if (i < 36864) { int oc = i / 576, k = i % 576; g_w3t[k * 64 + oc] = w3[i]; }
}

// ---------------- conv1: 3x48x64 -> 32x11x15, k8 s4 ------------------------
// one block per image; thread t<165 owns one spatial position, all 32 oc.
__global__ __launch_bounds__(192) void conv1_kernel(
    const float* __restrict__ x, const float* __restrict__ b1,
    float* __restrict__ ave1) {
    extern __shared__ float sm[];
    float* xs = sm;            // 9216 floats: [3][48][64]
    float* ws = sm + 9216;     // 6144 floats: [192][32]
    int b = blockIdx.x;
    const float* xb = x + (size_t)b * 9216;
    for (int i = threadIdx.x; i < 9216; i += blockDim.x) xs[i] = xb[i];
    for (int i = threadIdx.x; i < 6144; i += blockDim.x) ws[i] = g_w1t[i];
    __syncthreads();

    int t = threadIdx.x;
    if (t < 165) {
        int oy = t / 15, ox = t % 15;
        float acc[32];
#pragma unroll
        for (int j = 0; j < 32; j++) acc[j] = 0.0f;

        for (int ci = 0; ci < 3; ci++) {
            for (int ky = 0; ky < 8; ky++) {
                const float* row = xs + ci * 3072 + (oy * 4 + ky) * 64 + ox * 4;
                const float4* wk = (const float4*)ws + (ci * 64 + ky * 8) * 8;
#pragma unroll
                for (int kx = 0; kx < 8; kx++) {
                    float xv = row[kx];
                    const float4* wv = wk + kx * 8;
#pragma unroll
                    for (int j = 0; j < 8; j++) {
                        float4 w = wv[j];
                        acc[4 * j + 0] = fmaf(xv, w.x, acc[4 * j + 0]);
                        acc[4 * j + 1] = fmaf(xv, w.y, acc[4 * j + 1]);
                        acc[4 * j + 2] = fmaf(xv, w.z, acc[4 * j + 2]);
                        acc[4 * j + 3] = fmaf(xv, w.w, acc[4 * j + 3]);
                    }
                }
            }
        }
        float s = 0.0f;
        float* ab = g_a1 + (size_t)b * 5280;
#pragma unroll
        for (int j = 0; j < 32; j++) {
            float pre = acc[j] + __ldg(&b1[j]);
            s += pre;
            ab[j * 165 + t] = fmaxf(pre, 0.0f);
        }
        atomicAdd(&ave1[t], s * (1.0f / 32.0f));
    }
}

// ---------------- conv2: 32x11x15 -> 64x5x7, k3 s2 --------------------------
// persistent blocks: load 72KB transposed weights once, loop over images.
// thread t<280: pos = t%35, oc-group of 8 = t/35.
__global__ __launch_bounds__(288) void conv2_kernel(
    const float* __restrict__ b2, float* __restrict__ ave2) {
    extern __shared__ float sm[];
    float* ws   = sm;                  // 18432 floats [288][64]
    float* xs   = sm + 18432;          // 5280 floats  [32][165]
    float* sred = sm + 18432 + 5280;   // 35 floats

    for (int i = threadIdx.x; i < 18432; i += blockDim.x) ws[i] = g_w2t[i];
    int t = threadIdx.x;
    int pos = t % 35, grp = t / 35;
    int oy = pos / 7, ox = pos % 7;
    int oc0 = grp * 8;

    for (int b = blockIdx.x; b < 4096; b += gridDim.x) {
        __syncthreads();   // previous iteration fully consumed xs/sred
        const float* xb = g_a1 + (size_t)b * 5280;
        for (int i = threadIdx.x; i < 5280; i += blockDim.x) xs[i] = xb[i];
        if (t < 35) sred[t] = 0.0f;
        __syncthreads();

        if (t < 280) {
            float acc[8];
#pragma unroll
            for (int j = 0; j < 8; j++) acc[j] = 0.0f;
            const float* xpos = xs + oy * 30 + ox * 2;
            for (int ci = 0; ci < 32; ci++) {
                const float* xrow = xpos + ci * 165;
#pragma unroll
                for (int ky = 0; ky < 3; ky++) {
#pragma unroll
                    for (int kx = 0; kx < 3; kx++) {
                        float xv = xrow[ky * 15 + kx];
                        const float4* wv =
                            (const float4*)(ws + ((ci * 9 + ky * 3 + kx) << 6) + oc0);
                        float4 wa = wv[0], wb = wv[1];
                        acc[0] = fmaf(xv, wa.x, acc[0]);
                        acc[1] = fmaf(xv, wa.y, acc[1]);
                        acc[2] = fmaf(xv, wa.z, acc[2]);
                        acc[3] = fmaf(xv, wa.w, acc[3]);
                        acc[4] = fmaf(xv, wb.x, acc[4]);
                        acc[5] = fmaf(xv, wb.y, acc[5]);
                        acc[6] = fmaf(xv, wb.z, acc[6]);
                        acc[7] = fmaf(xv, wb.w, acc[7]);
                    }
                }
            }
            float s = 0.0f;
            float* ab = g_a2 + (size_t)b * 2240;
#pragma unroll
            for (int j = 0; j < 8; j++) {
                float pre = acc[j] + __ldg(&b2[oc0 + j]);
                s += pre;
                ab[(oc0 + j) * 35 + pos] = fmaxf(pre, 0.0f);
            }
            atomicAdd(&sred[pos], s * (1.0f / 64.0f));
        }
        __syncthreads();
        if (t < 35) atomicAdd(&ave2[t], sred[t]);
    }
}

// ---------------- conv3: 64x5x7 -> 64x3x5, k3 s1 ----------------------------
// one block per image; weights stay L1-resident (broadcast LDG.128).
// thread t<240: pos = t%15, oc-group of 4 = t/15.
__global__ __launch_bounds__(256) void conv3_kernel(
    const float* __restrict__ b3, float* __restrict__ ave3) {
    __shared__ float xs[2240];
    __shared__ float sred[15];
    int b = blockIdx.x;
    const float* xb = g_a2 + (size_t)b * 2240;
    for (int i = threadIdx.x; i < 2240; i += blockDim.x) xs[i] = xb[i];
    if (threadIdx.x < 15) sred[threadIdx.x] = 0.0f;
    __syncthreads();

    int t = threadIdx.x;
    if (t < 240) {
        int pos = t % 15, grp = t / 15;
        int oy = pos / 5, ox = pos % 5;
        int oc0 = grp * 4;
        float acc[4] = {0.0f, 0.0f, 0.0f, 0.0f};
        for (int ci = 0; ci < 64; ci++) {
            const float* xrow = xs + ci * 35 + oy * 7 + ox;
#pragma unroll
            for (int ky = 0; ky < 3; ky++) {
#pragma unroll
                for (int kx = 0; kx < 3; kx++) {
                    float xv = xrow[ky * 7 + kx];
                    float4 w = __ldg((const float4*)(g_w3t +
                                     ((ci * 9 + ky * 3 + kx) << 6) + oc0));
                    acc[0] = fmaf(xv, w.x, acc[0]);
                    acc[1] = fmaf(xv, w.y, acc[1]);
                    acc[2] = fmaf(xv, w.z, acc[2]);
                    acc[3] = fmaf(xv, w.w, acc[3]);
                }
            }
        }
        float s = 0.0f;
        float* ab = g_a3 + (size_t)b * 960;
#pragma unroll
        for (int j = 0; j < 4; j++) {
            float pre = acc[j] + __ldg(&b3[oc0 + j]);
            s += pre;
            ab[(oc0 + j) * 15 + pos] = fmaxf(pre, 0.0f);
        }
        atomicAdd(&sred[pos], s * (1.0f / 64.0f));
    }
    __syncthreads();
    if (t < 15) atomicAdd(&ave3[t], sred[t]);
}

// ---------------- fc1: [4096,960] x [512,960]^T + b, relu -------------------
// 64x64 tile per block, 256 threads, 4x4 per thread, pad-68 smem rows.
__global__ __launch_bounds__(256) void fc1_kernel(
    const float* __restrict__ W, const float* __restrict__ bias) {
    __shared__ float sa[16 * 68];
    __shared__ float sb[16 * 68];
    int m0 = blockIdx.x * 64;
    int n0 = blockIdx.y * 64;
    int tid = threadIdx.x;
    int tx = tid & 15;        // m sub-tile
    int ty = tid >> 4;        // n sub-tile
    int lm = tid >> 2;        // 0..63 loader row
    int lk = tid & 3;         // 0..3  loader float4 within k-slab

    float acc[4][4];
#pragma unroll
    for (int i = 0; i < 4; i++)
#pragma unroll
        for (int j = 0; j < 4; j++) acc[i][j] = 0.0f;

    const float* Arow = g_a3 + (size_t)(m0 + lm) * 960 + lk * 4;
    const float* Wrow = W    + (size_t)(n0 + lm) * 960 + lk * 4;

    for (int k0 = 0; k0 < 960; k0 += 16) {
        float4 av = *(const float4*)(Arow + k0);
        float4 bv = *(const float4*)(Wrow + k0);
        sa[(4 * lk + 0) * 68 + lm] = av.x;
        sa[(4 * lk + 1) * 68 + lm] = av.y;
        sa[(4 * lk + 2) * 68 + lm] = av.z;
        sa[(4 * lk + 3) * 68 + lm] = av.w;
        sb[(4 * lk + 0) * 68 + lm] = bv.x;
        sb[(4 * lk + 1) * 68 + lm] = bv.y;
        sb[(4 * lk + 2) * 68 + lm] = bv.z;
        sb[(4 * lk + 3) * 68 + lm] = bv.w;
        __syncthreads();
#pragma unroll
        for (int ki = 0; ki < 16; ki++) {
            float4 a4 = *(const float4*)&sa[ki * 68 + tx * 4];
            float4 b4 = *(const float4*)&sb[ki * 68 + ty * 4];
            float am[4] = {a4.x, a4.y, a4.z, a4.w};
            float bn[4] = {b4.x, b4.y, b4.z, b4.w};
#pragma unroll
            for (int i = 0; i < 4; i++)
#pragma unroll
                for (int j = 0; j < 4; j++)
                    acc[i][j] = fmaf(am[i], bn[j], acc[i][j]);
        }
        __syncthreads();
    }
    // epilogue: bias + relu, float4 stores along n
#pragma unroll
    for (int i = 0; i < 4; i++) {
        int m = m0 + tx * 4 + i;
        int n = n0 + ty * 4;
        float4 v;
        v.x = fmaxf(acc[i][0] + __ldg(&bias[n + 0]), 0.0f);
        v.y = fmaxf(acc[i][1] + __ldg(&bias[n + 1]), 0.0f);
        v.z = fmaxf(acc[i][2] + __ldg(&bias[n + 2]), 0.0f);
        v.w = fmaxf(acc[i][3] + __ldg(&bias[n + 3]), 0.0f);
        *(float4*)&g_h[(size_t)m * 512 + n] = v;
    }
}

// ---------------- fc2: [4096,512] x [2,512]^T + b ---------------------------
__global__ __launch_bounds__(256) void fc2_kernel(
    const float* __restrict__ w5, const float* __restrict__ b5,
    float* __restrict__ out) {
    int b = blockIdx.x * blockDim.x + threadIdx.x;
    if (b >= 4096) return;
    const float4* h4 = (const float4*)(g_h + (size_t)b * 512);
    const float4* wa = (const float4*)w5;
    const float4* wb = (const float4*)(w5 + 512);
    float s0 = 0.0f, s1 = 0.0f;
#pragma unroll 4
    for (int i = 0; i < 128; i++) {
        float4 h = h4[i];
        float4 a = __ldg(&wa[i]);
        float4 c = __ldg(&wb[i]);
        s0 += h.x * a.x + h.y * a.y + h.z * a.z + h.w * a.w;
        s1 += h.x * c.x + h.y * c.y + h.z * c.z + h.w * c.w;
    }
    out[b * 2 + 0] = s0 + __ldg(&b5[0]);
    out[b * 2 + 1] = s1 + __ldg(&b5[1]);
}

// ---------------- launch ----------------------------------------------------
extern "C" void kernel_launch(void* const* d_in, const int* in_sizes, int n_in,
                              void* d_out, int out_size) {
    const float* x  = (const float*)d_in[0];
    const float* w1 = (const float*)d_in[1];
    const float* b1 = (const float*)d_in[2];
    const float* w2 = (const float*)d_in[3];
    const float* b2 = (const float*)d_in[4];
    const float* w3 = (const float*)d_in[5];
    const float* b3 = (const float*)d_in[6];
    const float* w4 = (const float*)d_in[7];
    const float* b4 = (const float*)d_in[8];
    const float* w5 = (const float*)d_in[9];
    const float* b5 = (const float*)d_in[10];

    float* out  = (float*)d_out;
    float* ave1 = out + 8192;        // 165
    float* ave2 = out + 8192 + 165;  // 35
    float* ave3 = out + 8192 + 200;  // 15

    // opt-in dynamic smem (idempotent, capture-safe: not a stream op)
    cudaFuncSetAttribute(conv1_kernel,
                         cudaFuncAttributeMaxDynamicSharedMemorySize, 61440);
    cudaFuncSetAttribute(conv2_kernel,
                         cudaFuncAttributeMaxDynamicSharedMemorySize, 94992);

    prep_kernel<<<144, 256>>>(w1, w2, w3, ave1);
    conv1_kernel<<<4096, 192, 61440>>>(x, b1, ave1);
    conv2_kernel<<<296, 288, 94992>>>(b2, ave2);
    conv3_kernel<<<4096, 256>>>(b3, ave3);
    {
        dim3 grid(64, 8);
        fc1_kernel<<<grid, 256>>>(w4, b4);
    }
    fc2_kernel<<<16, 256>>>(w5, b5, out);
}

// round 3
// speedup vs baseline: 1.2789x; 1.2789x over previous
#include <cuda_runtime.h>
#include <cstddef>

typedef unsigned long long u64;

// ---------------- scratch (device globals; no allocations allowed) ----------
__device__ float g_a1[4096 * 5280];   // post-relu conv1: [b][32][11*15]
__device__ float g_a2[4096 * 2240];   // post-relu conv2: [b][64][5*7]
__device__ float g_a3[4096 * 960];    // post-relu conv3 (flatten CHW): [b][960]
__device__ float g_h [4096 * 512];    // post-relu fc1
__device__ float g_w1t[192 * 32];     // w transposed [k][oc]
__device__ float g_w2t[288 * 64];
__device__ float g_w3t[576 * 64];
__device__ float g_w4t[960 * 512];
__device__ int   g_off1[192];
__device__ int   g_off2[288];
__device__ int   g_off3[576];
__device__ int   g_off4[960];

// ---------------- f32x2 helpers ---------------------------------------------
__device__ __forceinline__ void fma2(u64& d, u64 a, u64 b) {
    asm("fma.rn.f32x2 %0, %1, %2, %3;" : "=l"(d) : "l"(a), "l"(b), "l"(d));
}
__device__ __forceinline__ void add2(u64& d, u64 a) {
    asm("add.rn.f32x2 %0, %1, %2;" : "=l"(d) : "l"(d), "l"(a));
}
__device__ __forceinline__ u64 dup2(float v) {
    u64 r; asm("mov.b64 %0, {%1, %1};" : "=l"(r) : "f"(v)); return r;
}
__device__ __forceinline__ void unpack2(u64 v, float& lo, float& hi) {
    asm("mov.b64 {%0, %1}, %2;" : "=f"(lo), "=f"(hi) : "l"(v));
}

// ---------------- prep: transpose weights + offset tables -------------------
__global__ void prep_kernel(const float* __restrict__ w1,
                            const float* __restrict__ w2,
                            const float* __restrict__ w3,
                            const float* __restrict__ w4) {
    int i = blockIdx.x * blockDim.x + threadIdx.x;
    if (i < 6144)   { int oc = i / 192, k = i % 192; g_w1t[k * 32 + oc] = w1[i]; }
    if (i < 18432)  { int oc = i / 288, k = i % 288; g_w2t[k * 64 + oc] = w2[i]; }
    if (i < 36864)  { int oc = i / 576, k = i % 576; g_w3t[k * 64 + oc] = w3[i]; }
    if (i < 491520) { int oc = i / 960, k = i % 960; g_w4t[k * 512 + oc] = w4[i]; }
    if (i < 192) { int ci = i >> 6, r = i & 63; g_off1[i] = ci * 3072 + (r >> 3) * 64 + (r & 7); }
    if (i < 288) { int ci = i / 9, r = i % 9;  g_off2[i] = ci * 165 + (r / 3) * 15 + r % 3; }
    if (i < 576) { int ci = i / 9, r = i % 9;  g_off3[i] = ci * 35  + (r / 3) * 7  + r % 3; }
    if (i < 960) g_off4[i] = i;
}

// init ave outputs to B*sum(bias)/C (the bias part of the pre-ReLU sums)
__global__ void aveinit_kernel(const float* __restrict__ b1,
                               const float* __restrict__ b2,
                               const float* __restrict__ b3,
                               float* __restrict__ out) {
    int t = threadIdx.x;
    if (t < 165) {
        float s = 0.f; for (int c = 0; c < 32; c++) s += b1[c];
        out[8192 + t] = 4096.f * s / 32.f;
    } else if (t < 200) {
        float s = 0.f; for (int c = 0; c < 64; c++) s += b2[c];
        out[8192 + 165 + (t - 165)] = 4096.f * s / 64.f;
    } else if (t < 215) {
        float s = 0.f; for (int c = 0; c < 64; c++) s += b3[c];
        out[8192 + 200 + (t - 200)] = 4096.f * s / 64.f;
    }
}

// ---------------- unified gather-GEMM (im2col conv / fc) --------------------
// Per-thread 8m x TYN n tile; acc are f32x2 m-pairs; B stored duplicated in
// smem so each LDS.128 gives two (b,b) pairs. A gathered via base+offset.
template<int TM, int TN, int TX, int TY, int LAYER, bool AVE, int MINB>
__global__ __launch_bounds__(TX * TY, MINB) void net_gemm(
    const float* __restrict__ src_ext,  // only used for LAYER==1 (input x)
    const float* __restrict__ bias,
    float* __restrict__ ave) {

    constexpr int NT  = TX * TY;
    constexpr int TYN = TN / TY;            // n per thread (4 or 8)
    constexpr int KPT = 16 * TM / NT;       // k-values per thread in A fill
    constexpr int NB  = 16 * TN / NT;       // b-values per thread in B fill
    static_assert(TM % (8 * TX) == 0 || TM == 8 * TX, "tile m");

    constexpr int K        = LAYER == 1 ? 192  : LAYER == 2 ? 288 : LAYER == 3 ? 576 : 960;
    constexpr int Ntot     = LAYER == 1 ? 32   : LAYER == 4 ? 512 : 64;
    constexpr int npos     = LAYER == 1 ? 165  : LAYER == 2 ? 35  : LAYER == 3 ? 15  : 1;
    constexpr int imgstr   = LAYER == 1 ? 9216 : LAYER == 2 ? 5280: LAYER == 3 ? 2240: 960;
    constexpr int PW       = LAYER == 1 ? 15   : LAYER == 2 ? 7   : LAYER == 3 ? 5   : 1;
    constexpr int rowstep  = LAYER == 1 ? 256  : LAYER == 2 ? 30  : LAYER == 3 ? 7   : 0;
    constexpr int colstep  = LAYER == 1 ? 4    : LAYER == 2 ? 2   : LAYER == 3 ? 1   : 0;
    constexpr int ocs      = LAYER == 1 ? 165  : LAYER == 2 ? 35  : LAYER == 3 ? 15  : 1;
    constexpr int cstride  = LAYER == 1 ? 5280 : LAYER == 2 ? 2240: LAYER == 3 ? 960 : 512;
    constexpr float invC   = LAYER == 1 ? (1.f / 32.f) : (1.f / 64.f);

    const float* wt;
    const int*   offtab;
    const float* src;
    float*       dst;
    if constexpr (LAYER == 1) { wt = g_w1t; offtab = g_off1; src = src_ext; dst = g_a1; }
    if constexpr (LAYER == 2) { wt = g_w2t; offtab = g_off2; src = g_a1;    dst = g_a2; }
    if constexpr (LAYER == 3) { wt = g_w3t; offtab = g_off3; src = g_a2;    dst = g_a3; }
    if constexpr (LAYER == 4) { wt = g_w4t; offtab = g_off4; src = g_a3;    dst = g_h;  }

    extern __shared__ float smem_[];
    float* sa   = smem_;                         // [16][TM]
    u64*   sbd  = (u64*)(sa + 16 * TM);          // [16][TN] duplicated pairs
    int*   soff = (int*)(sbd + 16 * TN);         // [K]
    int*   sbase = soff + K;                     // [TM]
    int*   sdst  = sbase + TM;                   // [TM]
    int*   spos  = sdst + TM;                    // [TM]
    float* sred  = (float*)(spos + TM);          // [TM]

    const int tid = threadIdx.x;
    const int m0 = blockIdx.x * TM;
    const int n0 = blockIdx.y * TN;

    for (int i = tid; i < K; i += NT) soff[i] = offtab[i];
    for (int i = tid; i < TM; i += NT) {
        int m = m0 + i;
        int img = m / npos, pos = m - img * npos;
        int py = pos / PW, px = pos - py * PW;
        sbase[i] = img * imgstr + py * rowstep + px * colstep;
        sdst[i]  = img * cstride + pos;
        if (AVE) { spos[i] = pos; sred[i] = 0.f; }
    }
    __syncthreads();

    const int mloc = tid % TM;
    const int k0f  = (tid / TM) * KPT;
    const int mybase = sbase[mloc];
    const int tx = tid % TX, ty = tid / TX;

    u64 acc[4][TYN];
#pragma unroll
    for (int p = 0; p < 4; p++)
#pragma unroll
        for (int j = 0; j < TYN; j++) acc[p][j] = 0ull;

    int bk[NB], bn[NB];
#pragma unroll
    for (int i = 0; i < NB; i++) { int q = tid + i * NT; bk[i] = q / TN; bn[i] = q % TN; }

    float ra[KPT], rbv[NB];
#pragma unroll
    for (int j = 0; j < KPT; j++) ra[j] = src[mybase + soff[k0f + j]];
#pragma unroll
    for (int i = 0; i < NB; i++) rbv[i] = wt[bk[i] * Ntot + n0 + bn[i]];

    const float* sao = sa + tx * 8;
    const u64*   sbo = sbd + ty * TYN;

    for (int kc = 0; kc < K; kc += 16) {
        __syncthreads();
#pragma unroll
        for (int j = 0; j < KPT; j++) sa[(k0f + j) * TM + mloc] = ra[j];
#pragma unroll
        for (int i = 0; i < NB; i++) sbd[bk[i] * TN + bn[i]] = dup2(rbv[i]);
        __syncthreads();
        if (kc + 16 < K) {
#pragma unroll
            for (int j = 0; j < KPT; j++) ra[j] = src[mybase + soff[kc + 16 + k0f + j]];
#pragma unroll
            for (int i = 0; i < NB; i++) rbv[i] = wt[(kc + 16 + bk[i]) * Ntot + n0 + bn[i]];
        }
#pragma unroll
        for (int k = 0; k < 16; k++) {
            ulonglong2 a0 = *(const ulonglong2*)(sao + k * TM);
            ulonglong2 a1 = *(const ulonglong2*)(sao + k * TM + 4);
            u64 ap[4] = {a0.x, a0.y, a1.x, a1.y};
            u64 bd[TYN];
#pragma unroll
            for (int c = 0; c < TYN / 2; c++) {
                ulonglong2 bv = *(const ulonglong2*)(sbo + k * TN + 2 * c);
                bd[2 * c] = bv.x; bd[2 * c + 1] = bv.y;
            }
#pragma unroll
            for (int p = 0; p < 4; p++)
#pragma unroll
                for (int j = 0; j < TYN; j++)
                    fma2(acc[p][j], ap[p], bd[j]);
        }
    }

    // epilogue
    float bnv[TYN];
#pragma unroll
    for (int j = 0; j < TYN; j++) bnv[j] = __ldg(&bias[n0 + ty * TYN + j]);

    if (AVE) {
#pragma unroll
        for (int p = 0; p < 4; p++) {
            u64 rs = acc[p][0];
#pragma unroll
            for (int j = 1; j < TYN; j++) add2(rs, acc[p][j]);
            float rl, rh; unpack2(rs, rl, rh);
            atomicAdd(&sred[tx * 8 + 2 * p], rl);
            atomicAdd(&sred[tx * 8 + 2 * p + 1], rh);
        }
    }
#pragma unroll
    for (int p = 0; p < 4; p++) {
        int dl = sdst[tx * 8 + 2 * p], dh = sdst[tx * 8 + 2 * p + 1];
#pragma unroll
        for (int j = 0; j < TYN; j++) {
            float lo, hi; unpack2(acc[p][j], lo, hi);
            int nn = n0 + ty * TYN + j;
            dst[dl + nn * ocs] = fmaxf(lo + bnv[j], 0.f);
            dst[dh + nn * ocs] = fmaxf(hi + bnv[j], 0.f);
        }
    }
    if (AVE) {
        __syncthreads();
        for (int i = tid; i < TM; i += NT)
            atomicAdd(&ave[spos[i]], sred[i] * invC);
    }
}

// ---------------- fc2: [4096,512] x [2,512]^T + b ---------------------------
__global__ __launch_bounds__(256) void fc2_kernel(
    const float* __restrict__ w5, const float* __restrict__ b5,
    float* __restrict__ out) {
    int b = blockIdx.x * blockDim.x + threadIdx.x;
    if (b >= 4096) return;
    const float4* h4 = (const float4*)(g_h + (size_t)b * 512);
    const float4* wa = (const float4*)w5;
    const float4* wb = (const float4*)(w5 + 512);
    float s0 = 0.0f, s1 = 0.0f;
#pragma unroll 4
    for (int i = 0; i < 128; i++) {
        float4 h = h4[i];
        float4 a = __ldg(&wa[i]);
        float4 c = __ldg(&wb[i]);
        s0 += h.x * a.x + h.y * a.y + h.z * a.z + h.w * a.w;
        s1 += h.x * c.x + h.y * c.y + h.z * c.z + h.w * c.w;
    }
    out[b * 2 + 0] = s0 + __ldg(&b5[0]);
    out[b * 2 + 1] = s1 + __ldg(&b5[1]);
}

// ---------------- launch ----------------------------------------------------
extern "C" void kernel_launch(void* const* d_in, const int* in_sizes, int n_in,
                              void* d_out, int out_size) {
    const float* x  = (const float*)d_in[0];
    const float* w1 = (const float*)d_in[1];
    const float* b1 = (const float*)d_in[2];
    const float* w2 = (const float*)d_in[3];
    const float* b2 = (const float*)d_in[4];
    const float* w3 = (const float*)d_in[5];
    const float* b3 = (const float*)d_in[6];
    const float* w4 = (const float*)d_in[7];
    const float* b4 = (const float*)d_in[8];
    const float* w5 = (const float*)d_in[9];
    const float* b5 = (const float*)d_in[10];

    float* out  = (float*)d_out;
    float* ave1 = out + 8192;        // 165
    float* ave2 = out + 8192 + 165;  // 35
    float* ave3 = out + 8192 + 200;  // 15

    prep_kernel<<<1920, 256>>>(w1, w2, w3, w4);
    aveinit_kernel<<<1, 256>>>(b1, b2, b3, out);

    // smem bytes: 64*TM + 128*TN + 4*K + 16*TM  (all < 48KB, no attr needed)
    // conv1: TM=128 TN=32  K=192 -> 15104 ; M=675840/128 = 5280 blocks
    net_gemm<128, 32, 16, 8, 1, true, 3><<<5280, 128, 15104>>>(x, b1, ave1);
    // conv2: TM=256 TN=64  K=288 -> 29824 ; M=143360/256 = 560 blocks
    net_gemm<256, 64, 32, 8, 2, true, 2><<<560, 256, 29824>>>(nullptr, b2, ave2);
    // conv3: TM=256 TN=64  K=576 -> 30976 ; M=61440/256 = 240 blocks
    net_gemm<256, 64, 32, 8, 3, true, 2><<<240, 256, 30976>>>(nullptr, b3, ave3);
    // fc1:   TM=128 TN=128 K=960 -> 30464 ; grid (4096/128, 512/128)
    {
        dim3 grid(32, 4);
        net_gemm<128, 128, 16, 16, 4, false, 2><<<grid, 256, 30464>>>(nullptr, b4, nullptr);
    }
    fc2_kernel<<<16, 256>>>(w5, b5, out);
}

// round 4
// speedup vs baseline: 1.3415x; 1.0490x over previous
#include <cuda_runtime.h>
#include <cstddef>

typedef unsigned long long u64;

// ---------------- scratch (device globals; no allocations allowed) ----------
__device__ float g_a1[4096 * 5280];   // post-relu conv1: [b][32][11*15]
__device__ float g_a2[4096 * 2240];   // post-relu conv2: [b][64][5*7]
__device__ float g_a3[4096 * 960];    // post-relu conv3 (flatten CHW): [b][960]
__device__ float g_h [4096 * 512];    // post-relu fc1
__device__ float g_w1t[192 * 32];     // w transposed [k][oc]
__device__ float g_w2t[288 * 64];
__device__ float g_w3t[576 * 64];
__device__ float g_w4t[960 * 512];
__device__ int   g_off1[192];
__device__ int   g_off2[288];
__device__ int   g_off3[576];
__device__ int   g_off4[960];

// ---------------- f32x2 helpers ---------------------------------------------
__device__ __forceinline__ void fma2(u64& d, u64 a, u64 b) {
    asm("fma.rn.f32x2 %0, %1, %2, %3;" : "=l"(d) : "l"(a), "l"(b), "l"(d));
}
__device__ __forceinline__ void add2(u64& d, u64 a) {
    asm("add.rn.f32x2 %0, %1, %2;" : "=l"(d) : "l"(d), "l"(a));
}
__device__ __forceinline__ u64 dup2(float v) {
    u64 r; asm("mov.b64 %0, {%1, %1};" : "=l"(r) : "f"(v)); return r;
}
__device__ __forceinline__ void unpack2(u64 v, float& lo, float& hi) {
    asm("mov.b64 {%0, %1}, %2;" : "=f"(lo), "=f"(hi) : "l"(v));
}

// ---------------- prep: transpose weights + offset tables -------------------
__global__ void prep_kernel(const float* __restrict__ w1,
                            const float* __restrict__ w2,
                            const float* __restrict__ w3,
                            const float* __restrict__ w4) {
    int i = blockIdx.x * blockDim.x + threadIdx.x;
    if (i < 6144)   { int oc = i / 192, k = i % 192; g_w1t[k * 32 + oc] = w1[i]; }
    if (i < 18432)  { int oc = i / 288, k = i % 288; g_w2t[k * 64 + oc] = w2[i]; }
    if (i < 36864)  { int oc = i / 576, k = i % 576; g_w3t[k * 64 + oc] = w3[i]; }
    if (i < 491520) { int oc = i / 960, k = i % 960; g_w4t[k * 512 + oc] = w4[i]; }
    if (i < 192) { int ci = i >> 6, r = i & 63; g_off1[i] = ci * 3072 + (r >> 3) * 64 + (r & 7); }
    if (i < 288) { int ci = i / 9, r = i % 9;  g_off2[i] = ci * 165 + (r / 3) * 15 + r % 3; }
    if (i < 576) { int ci = i / 9, r = i % 9;  g_off3[i] = ci * 35  + (r / 3) * 7  + r % 3; }
    if (i < 960) g_off4[i] = i;
}

// init ave outputs to B*sum(bias)/C (the bias part of the pre-ReLU sums)
__global__ void aveinit_kernel(const float* __restrict__ b1,
                               const float* __restrict__ b2,
                               const float* __restrict__ b3,
                               float* __restrict__ out) {
    int t = threadIdx.x;
    if (t < 165) {
        float s = 0.f; for (int c = 0; c < 32; c++) s += b1[c];
        out[8192 + t] = 4096.f * s / 32.f;
    } else if (t < 200) {
        float s = 0.f; for (int c = 0; c < 64; c++) s += b2[c];
        out[8192 + 165 + (t - 165)] = 4096.f * s / 64.f;
    } else if (t < 215) {
        float s = 0.f; for (int c = 0; c < 64; c++) s += b3[c];
        out[8192 + 200 + (t - 200)] = 4096.f * s / 64.f;
    }
}

// ---------------- unified gather-GEMM (im2col conv / fc) --------------------
// TX=32 fixed: B smem loads are warp-broadcast. A per-thread m-tile is split
// into H=TM/128 half-tiles at tx*4 / TM/2+tx*4 -> conflict-free 512B warp
// loads. Double-buffered smem, KC=8, one __syncthreads per chunk.
template<int TM, int TN, int TY, int LAYER, bool AVE, int MINB>
__global__ __launch_bounds__(32 * TY, MINB) void net_gemm(
    const float* __restrict__ src_ext,  // only used for LAYER==1 (input x)
    const float* __restrict__ bias,
    float* __restrict__ ave) {

    constexpr int NT  = 32 * TY;
    constexpr int KC  = 8;                  // k per chunk
    constexpr int TYN = TN / TY;            // n per thread (4 or 8)
    constexpr int P   = TM / 64;            // f32x2 m-pairs per thread (2 or 4)
    constexpr int H   = TM / 128;           // m half-tiles (1 or 2)
    constexpr int KPT = KC * TM / NT;       // A elems per thread per chunk
    constexpr int NB  = KC * TN / NT;       // B elems per thread per chunk

    constexpr int K        = LAYER == 1 ? 192  : LAYER == 2 ? 288 : LAYER == 3 ? 576 : 960;
    constexpr int NC       = K / KC;
    constexpr int Ntot     = LAYER == 1 ? 32   : LAYER == 4 ? 512 : 64;
    constexpr int npos     = LAYER == 1 ? 165  : LAYER == 2 ? 35  : LAYER == 3 ? 15  : 1;
    constexpr int imgstr   = LAYER == 1 ? 9216 : LAYER == 2 ? 5280: LAYER == 3 ? 2240: 960;
    constexpr int PW       = LAYER == 1 ? 15   : LAYER == 2 ? 7   : LAYER == 3 ? 5   : 1;
    constexpr int rowstep  = LAYER == 1 ? 256  : LAYER == 2 ? 30  : LAYER == 3 ? 7   : 0;
    constexpr int colstep  = LAYER == 1 ? 4    : LAYER == 2 ? 2   : LAYER == 3 ? 1   : 0;
    constexpr int ocs      = LAYER == 1 ? 165  : LAYER == 2 ? 35  : LAYER == 3 ? 15  : 1;
    constexpr int cstride  = LAYER == 1 ? 5280 : LAYER == 2 ? 2240: LAYER == 3 ? 960 : 512;
    constexpr float invC   = LAYER == 1 ? (1.f / 32.f) : (1.f / 64.f);

    const float* wt;
    const int*   offtab;
    const float* src;
    float*       dst;
    if constexpr (LAYER == 1) { wt = g_w1t; offtab = g_off1; src = src_ext; dst = g_a1; }
    if constexpr (LAYER == 2) { wt = g_w2t; offtab = g_off2; src = g_a1;    dst = g_a2; }
    if constexpr (LAYER == 3) { wt = g_w3t; offtab = g_off3; src = g_a2;    dst = g_a3; }
    if constexpr (LAYER == 4) { wt = g_w4t; offtab = g_off4; src = g_a3;    dst = g_h;  }

    extern __shared__ float smem_[];
    float* sa    = smem_;                          // [2][KC][TM]
    u64*   sbd   = (u64*)(sa + 2 * KC * TM);       // [2][KC][TN] dup pairs
    int*   soff  = (int*)(sbd + 2 * KC * TN);      // [K]
    int*   sbase = soff + K;                       // [TM]
    int*   sdst  = sbase + TM;                     // [TM]
    int*   spos  = sdst + TM;                      // [TM] (AVE)
    float* sred  = (float*)(spos + TM);            // [TM] (AVE)

    const int tid = threadIdx.x;
    const int m0 = blockIdx.x * TM;
    const int n0 = blockIdx.y * TN;

    for (int i = tid; i < K; i += NT) soff[i] = offtab[i];
    for (int i = tid; i < TM; i += NT) {
        int m = m0 + i;
        int img = m / npos, pos = m - img * npos;
        int py = pos / PW, px = pos - py * PW;
        sbase[i] = img * imgstr + py * rowstep + px * colstep;
        sdst[i]  = img * cstride + pos;
        if (AVE) { spos[i] = pos; sred[i] = 0.f; }
    }
    __syncthreads();

    const int mloc = tid % TM;
    const int k0f  = (tid / TM) * KPT;
    const int mybase = sbase[mloc];
    const int tx = tid & 31, ty = tid >> 5;

    u64 acc[P][TYN];
#pragma unroll
    for (int p = 0; p < P; p++)
#pragma unroll
        for (int j = 0; j < TYN; j++) acc[p][j] = 0ull;

    int bk[NB], bn[NB];
#pragma unroll
    for (int i = 0; i < NB; i++) { int q = tid + i * NT; bk[i] = q / TN; bn[i] = q % TN; }

    float ra[KPT], rbv[NB];
    // prologue: chunk 0 -> regs -> buf0
#pragma unroll
    for (int j = 0; j < KPT; j++) ra[j] = src[mybase + soff[k0f + j]];
#pragma unroll
    for (int i = 0; i < NB; i++) rbv[i] = wt[bk[i] * Ntot + n0 + bn[i]];
#pragma unroll
    for (int j = 0; j < KPT; j++) sa[(k0f + j) * TM + mloc] = ra[j];
#pragma unroll
    for (int i = 0; i < NB; i++) sbd[bk[i] * TN + bn[i]] = dup2(rbv[i]);
    __syncthreads();

    const float* sax = sa + tx * 4;
    const u64*   sbx = sbd + ty * TYN;

    for (int kc = 0; kc < NC; kc++) {
        const int cur = kc & 1;
        if (kc + 1 < NC) {
            const int kg = (kc + 1) * KC;
#pragma unroll
            for (int j = 0; j < KPT; j++) ra[j] = src[mybase + soff[kg + k0f + j]];
#pragma unroll
            for (int i = 0; i < NB; i++) rbv[i] = wt[(kg + bk[i]) * Ntot + n0 + bn[i]];
        }
        const float* sac = sax + cur * KC * TM;
        const u64*   sbc = sbx + cur * KC * TN;
#pragma unroll
        for (int k = 0; k < KC; k++) {
            u64 ap[P];
#pragma unroll
            for (int h = 0; h < H; h++) {
                ulonglong2 a = *(const ulonglong2*)(sac + k * TM + h * (TM / 2));
                ap[2 * h] = a.x; ap[2 * h + 1] = a.y;
            }
            u64 bd[TYN];
#pragma unroll
            for (int c = 0; c < TYN / 2; c++) {
                ulonglong2 bv = *(const ulonglong2*)(sbc + k * TN + 2 * c);
                bd[2 * c] = bv.x; bd[2 * c + 1] = bv.y;
            }
#pragma unroll
            for (int p = 0; p < P; p++)
#pragma unroll
                for (int j = 0; j < TYN; j++)
                    fma2(acc[p][j], ap[p], bd[j]);
        }
        if (kc + 1 < NC) {
            const int nb = cur ^ 1;
#pragma unroll
            for (int j = 0; j < KPT; j++) sa[nb * KC * TM + (k0f + j) * TM + mloc] = ra[j];
#pragma unroll
            for (int i = 0; i < NB; i++) sbd[nb * KC * TN + bk[i] * TN + bn[i]] = dup2(rbv[i]);
            __syncthreads();
        }
    }

    // epilogue
    float bnv[TYN];
#pragma unroll
    for (int j = 0; j < TYN; j++) bnv[j] = __ldg(&bias[n0 + ty * TYN + j]);

    int ml[P];
#pragma unroll
    for (int p = 0; p < P; p++) ml[p] = (p & 1) * 2 + (p >> 1) * (TM / 2) + tx * 4;

    if (AVE) {
#pragma unroll
        for (int p = 0; p < P; p++) {
            u64 rs = acc[p][0];
#pragma unroll
            for (int j = 1; j < TYN; j++) add2(rs, acc[p][j]);
            float rl, rh; unpack2(rs, rl, rh);
            atomicAdd(&sred[ml[p]], rl);
            atomicAdd(&sred[ml[p] + 1], rh);
        }
    }
#pragma unroll
    for (int p = 0; p < P; p++) {
        int dl = sdst[ml[p]], dh = sdst[ml[p] + 1];
#pragma unroll
        for (int j = 0; j < TYN; j++) {
            float lo, hi; unpack2(acc[p][j], lo, hi);
            int nn = n0 + ty * TYN + j;
            dst[dl + nn * ocs] = fmaxf(lo + bnv[j], 0.f);
            dst[dh + nn * ocs] = fmaxf(hi + bnv[j], 0.f);
        }
    }
    if (AVE) {
        __syncthreads();
        for (int i = tid; i < TM; i += NT)
            atomicAdd(&ave[spos[i]], sred[i] * invC);
    }
}

// ---------------- fc2: [4096,512] x [2,512]^T + b ---------------------------
__global__ __launch_bounds__(256) void fc2_kernel(
    const float* __restrict__ w5, const float* __restrict__ b5,
    float* __restrict__ out) {
    int b = blockIdx.x * blockDim.x + threadIdx.x;
    if (b >= 4096) return;
    const float4* h4 = (const float4*)(g_h + (size_t)b * 512);
    const float4* wa = (const float4*)w5;
    const float4* wb = (const float4*)(w5 + 512);
    float s0 = 0.0f, s1 = 0.0f;
#pragma unroll 4
    for (int i = 0; i < 128; i++) {
        float4 h = h4[i];
        float4 a = __ldg(&wa[i]);
        float4 c = __ldg(&wb[i]);
        s0 += h.x * a.x + h.y * a.y + h.z * a.z + h.w * a.w;
        s1 += h.x * c.x + h.y * c.y + h.z * c.z + h.w * c.w;
    }
    out[b * 2 + 0] = s0 + __ldg(&b5[0]);
    out[b * 2 + 1] = s1 + __ldg(&b5[1]);
}

// ---------------- launch ----------------------------------------------------
extern "C" void kernel_launch(void* const* d_in, const int* in_sizes, int n_in,
                              void* d_out, int out_size) {
    const float* x  = (const float*)d_in[0];
    const float* w1 = (const float*)d_in[1];
    const float* b1 = (const float*)d_in[2];
    const float* w2 = (const float*)d_in[3];
    const float* b2 = (const float*)d_in[4];
    const float* w3 = (const float*)d_in[5];
    const float* b3 = (const float*)d_in[6];
    const float* w4 = (const float*)d_in[7];
    const float* b4 = (const float*)d_in[8];
    const float* w5 = (const float*)d_in[9];
    const float* b5 = (const float*)d_in[10];

    float* out  = (float*)d_out;
    float* ave1 = out + 8192;        // 165
    float* ave2 = out + 8192 + 165;  // 35
    float* ave3 = out + 8192 + 200;  // 15

    prep_kernel<<<1920, 256>>>(w1, w2, w3, w4);
    aveinit_kernel<<<1, 256>>>(b1, b2, b3, out);

    // smem (bytes) = 4*(2*8*TM) + 8*(2*8*TN) + 4*K + 16*TM (12*TM if !AVE)
    // conv1: TM=256 TN=32 K=192 -> 16384+4096+768+4096  = 25344
    net_gemm<256, 32, 8, 1, true, 2><<<2640, 256, 25344>>>(x, b1, ave1);
    // conv2: TM=256 TN=64 K=288 -> 16384+8192+1152+4096 = 29824
    net_gemm<256, 64, 8, 2, true, 2><<<560, 256, 29824>>>(nullptr, b2, ave2);
    // conv3: TM=128 TN=64 K=576 -> 8192+8192+2304+2048  = 20736
    net_gemm<128, 64, 8, 3, true, 3><<<480, 256, 20736>>>(nullptr, b3, ave3);
    // fc1:   TM=128 TN=64 K=960 -> 8192+8192+3840+2048(ok to over-ask) = 22272
    {
        dim3 grid(32, 8);
        net_gemm<128, 64, 8, 4, false, 3><<<grid, 256, 22272>>>(nullptr, b4, nullptr);
    }
    fc2_kernel<<<16, 256>>>(w5, b5, out);
}